// round 2
// baseline (speedup 1.0000x reference)
#include <cuda_runtime.h>
#include <math.h>

#define BATCH 32768
#define DIM   256
#define CBK   1024
#define LVL   8

#define BM  128
#define BN  128
#define BMP 132                      // padded row stride (floats) for smem tiles

#define SMEM_BYTES (256*BMP*4 + 2*8*BMP*4 + 256*4 + 128*4)  // A_s + B_s(double) + s_red + s_idx

// ---------------- device scratch (static globals: allocation-free) ----------------
__device__ float g_resid[BATCH * DIM];        // 32 MB
__device__ float g_qsum [BATCH * DIM];        // 32 MB
__device__ float g_xx   [BATCH];
__device__ float g_ee   [LVL * CBK];
__device__ int   g_idx  [BATCH * LVL];
__device__ float g_commit_part[LVL * 256];
__device__ int   g_counts[CBK];

// ---------------- small utility kernels ----------------
__global__ void k_init()
{
    int t = blockIdx.x * blockDim.x + threadIdx.x;
    if (t < CBK) g_counts[t] = 0;
}

// squared row norms of the codebooks: 8192 codes, one warp per code
__global__ void k_ee(const float* __restrict__ emb)
{
    int gw   = blockIdx.x * (blockDim.x >> 5) + (threadIdx.x >> 5);
    int lane = threadIdx.x & 31;
    if (gw >= LVL * CBK) return;
    const float* r = emb + (size_t)gw * DIM;
    float s = 0.f;
#pragma unroll
    for (int j = 0; j < 8; j++) { float v = r[lane + 32 * j]; s = fmaf(v, v, s); }
#pragma unroll
    for (int o = 16; o; o >>= 1) s += __shfl_xor_sync(0xffffffffu, s, o);
    if (!lane) g_ee[gw] = s;
}

// squared row norms of z (level-0 xx): one warp per row
__global__ void k_xx0(const float* __restrict__ z)
{
    int gw   = blockIdx.x * (blockDim.x >> 5) + (threadIdx.x >> 5);
    int lane = threadIdx.x & 31;
    if (gw >= BATCH) return;
    const float* r = z + (size_t)gw * DIM;
    float s = 0.f;
#pragma unroll
    for (int j = 0; j < 8; j++) { float v = r[lane + 32 * j]; s = fmaf(v, v, s); }
#pragma unroll
    for (int o = 16; o; o >>= 1) s += __shfl_xor_sync(0xffffffffu, s, o);
    if (!lane) g_xx[gw] = s;
}

// ---------------- main per-level kernel: GEMM + argmin + residual update ----------------
// Block: 256 threads (16 tx x 16 ty). BM=128 rows fully resident in smem (transposed).
// Loops over 8 code tiles of 128; B slabs [8 k][128 codes] double-buffered with
// register prefetch. Thread micro-tile 8x8. Fused epilogue: argmin reduce, write idx,
// residual -= e[idx], qsum += e[idx], next-level xx, commit partial.
__global__ void __launch_bounds__(256, 1)
k_level(const float* __restrict__ z,
        const float* __restrict__ cb,     // this level's codebook [1024][256]
        int level,
        float* __restrict__ o_idx_f)      // d_out indices region (float) or null
{
    extern __shared__ float sm[];
    float* A_s   = sm;                     // [256][BMP]
    float* B_s   = sm + 256 * BMP;         // [2][8][BMP]
    float* s_red = B_s + 2 * 8 * BMP;      // [256]
    int*   s_idx = (int*)(s_red + 256);    // [128]

    const int tid  = threadIdx.x;
    const int tx   = tid & 15;
    const int ty   = tid >> 4;
    const int row0 = blockIdx.x * BM;
    const int first = (level == 0);
    const float* A_src = first ? z : g_resid;

    // ---- load A tile, store transposed [dim][row] (conflict-free STS) ----
    {
        int r = tid & 127, half = tid >> 7;
        const float* src = A_src + (size_t)(row0 + r) * DIM + half * 128;
#pragma unroll 8
        for (int i = 0; i < 32; i++) {
            float4 v = *(const float4*)(src + i * 4);
            int d = half * 128 + i * 4;
            A_s[(d + 0) * BMP + r] = v.x;
            A_s[(d + 1) * BMP + r] = v.y;
            A_s[(d + 2) * BMP + r] = v.z;
            A_s[(d + 3) * BMP + r] = v.w;
        }
    }

    float xx_r[8];
#pragma unroll
    for (int i = 0; i < 8; i++) xx_r[i] = g_xx[row0 + ty * 8 + i];

    float acc[8][8];
#pragma unroll
    for (int i = 0; i < 8; i++)
#pragma unroll
        for (int j = 0; j < 8; j++) acc[i][j] = 0.f;

    float bval[8]; int bidx[8];
#pragma unroll
    for (int i = 0; i < 8; i++) { bval[i] = 3.4e38f; bidx[i] = 0; }

    const int c = tid >> 1, kk4 = (tid & 1) << 2;
    float4 pre = *(const float4*)&cb[(size_t)c * DIM + kk4];   // slab 0 (tile 0, k0=0)

    // 8 code tiles x 32 k-slabs = 256 slab steps
    for (int s = 0; s < 256; s++) {
        __syncthreads();
        float* Bb = B_s + (s & 1) * (8 * BMP);
        Bb[(kk4 + 0) * BMP + c] = pre.x;
        Bb[(kk4 + 1) * BMP + c] = pre.y;
        Bb[(kk4 + 2) * BMP + c] = pre.z;
        Bb[(kk4 + 3) * BMP + c] = pre.w;
        __syncthreads();
        if (s + 1 < 256) {
            int t2 = (s + 1) >> 5, k02 = ((s + 1) & 31) << 3;
            pre = *(const float4*)&cb[(size_t)((t2 << 7) + c) * DIM + k02 + kk4];
        }
        int k0 = (s & 31) << 3;
#pragma unroll
        for (int kk = 0; kk < 8; kk++) {
            const float* arow = &A_s[(k0 + kk) * BMP + ty * 8];
            float4 a0 = *(const float4*)arow;
            float4 a1 = *(const float4*)(arow + 4);
            const float* brow = &Bb[kk * BMP + tx * 8];
            float4 b0 = *(const float4*)brow;
            float4 b1 = *(const float4*)(brow + 4);
            float av[8] = {a0.x, a0.y, a0.z, a0.w, a1.x, a1.y, a1.z, a1.w};
            float bv[8] = {b0.x, b0.y, b0.z, b0.w, b1.x, b1.y, b1.z, b1.w};
#pragma unroll
            for (int i = 0; i < 8; i++)
#pragma unroll
                for (int j = 0; j < 8; j++)
                    acc[i][j] = fmaf(av[i], bv[j], acc[i][j]);
        }
        if ((s & 31) == 31) {          // finished one code tile: score + track min
            int n0 = (s >> 5) << 7;
#pragma unroll
            for (int j = 0; j < 8; j++) {
                int col = n0 + tx * 8 + j;
                float ev = g_ee[level * CBK + col];
#pragma unroll
                for (int i = 0; i < 8; i++) {
                    float t1 = xx_r[i] + ev;              // matches (xx + ee)
                    float dd = t1 - 2.0f * acc[i][j];     // matches ... - 2*m (2*acc exact)
                    if (dd < bval[i]) { bval[i] = dd; bidx[i] = col; }  // ties keep lower col
                    acc[i][j] = 0.f;
                }
            }
        }
    }

    // ---- per-row argmin across the 16 tx lanes (same half-warp), lowest-index ties ----
#pragma unroll
    for (int i = 0; i < 8; i++) {
        float v = bval[i]; int ix = bidx[i];
#pragma unroll
        for (int o = 8; o; o >>= 1) {
            float ov = __shfl_down_sync(0xffffffffu, v, o, 16);
            int   oi = __shfl_down_sync(0xffffffffu, ix, o, 16);
            if (ov < v || (ov == v && oi < ix)) { v = ov; ix = oi; }
        }
        if (tx == 0) {
            int lr = ty * 8 + i;
            s_idx[lr] = ix;
            int gr = row0 + lr;
            g_idx[(size_t)gr * LVL + level] = ix;
            if (o_idx_f) o_idx_f[(size_t)gr * LVL + level] = (float)ix;
        }
    }
    __syncthreads();

    // ---- fused epilogue: residual update, qsum accumulate, next xx, commit partial ----
    {
        int r2 = tid >> 1, dh = (tid & 1) << 7;     // 2 threads per row, 128 dims each
        int gi = s_idx[r2];
        const float* ev = cb + (size_t)gi * DIM + dh;
        size_t gofs = (size_t)(row0 + r2) * DIM + dh;
        float* ro = g_resid + gofs;
        float* qo = g_qsum + gofs;
        float ss = 0.f;
#pragma unroll 4
        for (int j = 0; j < 32; j++) {
            int d = dh + j * 4;
            float a0 = A_s[(d + 0) * BMP + r2];
            float a1 = A_s[(d + 1) * BMP + r2];
            float a2 = A_s[(d + 2) * BMP + r2];
            float a3 = A_s[(d + 3) * BMP + r2];
            float4 e = *(const float4*)(ev + j * 4);
            float4 rn = make_float4(a0 - e.x, a1 - e.y, a2 - e.z, a3 - e.w);
            *(float4*)(ro + j * 4) = rn;
            float4 q;
            if (first) q = e;
            else {
                float4 qp = *(const float4*)(qo + j * 4);
                q = make_float4(qp.x + e.x, qp.y + e.y, qp.z + e.z, qp.w + e.w);
            }
            *(float4*)(qo + j * 4) = q;
            ss = fmaf(rn.x, rn.x, ss); ss = fmaf(rn.y, rn.y, ss);
            ss = fmaf(rn.z, rn.z, ss); ss = fmaf(rn.w, rn.w, ss);
        }
        s_red[tid] = ss;
        __syncthreads();
        if (!(tid & 1)) g_xx[row0 + r2] = s_red[tid] + s_red[tid | 1];  // next-level ||r||^2
        __syncthreads();
#pragma unroll
        for (int o = 128; o; o >>= 1) {
            if (tid < o) s_red[tid] += s_red[tid + o];
            __syncthreads();
        }
        if (!tid) g_commit_part[level * 256 + blockIdx.x] = s_red[0];
    }
}

// ---------------- histogram of indices ----------------
__global__ void k_count()
{
    __shared__ int h[CBK];
    for (int i = threadIdx.x; i < CBK; i += blockDim.x) h[i] = 0;
    __syncthreads();
    int stride = gridDim.x * blockDim.x;
    for (int i = blockIdx.x * blockDim.x + threadIdx.x; i < BATCH * LVL; i += stride)
        atomicAdd(&h[g_idx[i]], 1);
    __syncthreads();
    for (int i = threadIdx.x; i < CBK; i += blockDim.x) {
        int v = h[i];
        if (v) atomicAdd(&g_counts[i], v);
    }
}

// ---------------- z_q = z + (qsum - z), replicating reference rounding ----------------
__global__ void k_zq(const float* __restrict__ z, float* __restrict__ out)
{
    int n = BATCH * DIM / 4;
    for (int i = blockIdx.x * blockDim.x + threadIdx.x; i < n; i += gridDim.x * blockDim.x) {
        float4 zv = ((const float4*)z)[i];
        float4 qv = ((const float4*)g_qsum)[i];
        float4 t = make_float4(qv.x - zv.x, qv.y - zv.y, qv.z - zv.z, qv.w - zv.w);
        ((float4*)out)[i] = make_float4(zv.x + t.x, zv.y + t.y, zv.z + t.z, zv.w + t.w);
    }
}

// ---------------- scalars: entropy/perplexity + commit totals ----------------
__global__ void k_final(float* __restrict__ o_sc)
{
    __shared__ float se[1024];
    __shared__ float sc[LVL];
    int t = threadIdx.x;
    // entropy partial
    float p = (float)g_counts[t] / 262144.0f;             // exact: /2^18
    se[t] = (p > 0.f) ? p * logf(p + 1e-10f) : 0.f;
    __syncthreads();
#pragma unroll
    for (int o = 512; o; o >>= 1) {
        if (t < o) se[t] += se[t + o];
        __syncthreads();
    }
    // commit totals: warp l reduces level l's 256 partials (warps 0..7)
    int w = t >> 5, lane = t & 31;
    if (w < LVL) {
        float s = 0.f;
        for (int b = lane; b < 256; b += 32) s += g_commit_part[w * 256 + b];
#pragma unroll
        for (int o = 16; o; o >>= 1) s += __shfl_xor_sync(0xffffffffu, s, o);
        if (!lane) sc[w] = s;
    }
    __syncthreads();
    if (!t && o_sc) {
        float ent = -se[0];
        float total = 0.f;
        for (int l = 0; l < LVL; l++) total += sc[l] / 8388608.0f;  // exact: /2^23 (jnp.mean)
        o_sc[0] = 0.25f * total;                          // vq_loss
        o_sc[1] = total;                                  // total_commit
        o_sc[2] = expf(ent);                              // perplexity
    }
}

// ---------------- launch ----------------
extern "C" void kernel_launch(void* const* d_in, const int* in_sizes, int n_in,
                              void* d_out, int out_size)
{
    const float* z   = (const float*)d_in[0];
    const float* emb = (const float*)d_in[1];
    // defensive: identify by size if the order is swapped
    if (n_in >= 2 && in_sizes[0] == LVL * CBK * DIM && in_sizes[1] == BATCH * DIM) {
        emb = (const float*)d_in[0];
        z   = (const float*)d_in[1];
    }

    cudaFuncSetAttribute(k_level, cudaFuncAttributeMaxDynamicSharedMemorySize, SMEM_BYTES);

    float* out = (float*)d_out;
    const long NZQ = (long)BATCH * DIM;   // 8388608
    const long NI  = (long)BATCH * LVL;   // 262144
    float* o_zq  = ((long)out_size >= NZQ)          ? out             : nullptr;
    float* o_idx = ((long)out_size >= NZQ + NI)     ? out + NZQ       : nullptr;
    float* o_sc  = ((long)out_size >= NZQ + NI + 3) ? out + NZQ + NI  : nullptr;

    k_init<<<1, 1024>>>();
    k_ee<<<(LVL * CBK) / 8, 256>>>(emb);
    k_xx0<<<BATCH / 8, 256>>>(z);
    for (int l = 0; l < LVL; l++)
        k_level<<<256, 256, SMEM_BYTES>>>(z, emb + (size_t)l * CBK * DIM, l, o_idx);
    k_count<<<64, 256>>>();
    if (o_zq) k_zq<<<2048, 256>>>(z, o_zq);
    k_final<<<1, 1024>>>(o_sc);
}